// round 15
// baseline (speedup 1.0000x reference)
#include <cuda_runtime.h>
#include <cuda.h>
#include <math.h>
#include <stdint.h>

#define BB   2
#define SS   2048
#define DD   1024
#define HH   16
#define DKK  64
#define MM   (BB * SS)

__device__ float g_Qh[MM * DD];
__device__ float g_Kh[MM * DD];
__device__ float g_Vh[MM * DD];
__device__ float g_Ctx[MM * DD];

// ---------------- PTX helpers --------------------------------------------------
__device__ __forceinline__ uint32_t f2tf32(float x) {
    uint32_t r; asm("cvt.rna.tf32.f32 %0, %1;\n" : "=r"(r) : "f"(x)); return r;
}
__device__ __forceinline__ float rndtf(float x) { return __uint_as_float(f2tf32(x)); }

__device__ __forceinline__ void mma_tf32(float c[4], const uint32_t a[4], const uint32_t b[2]) {
    asm volatile(
        "mma.sync.aligned.m16n8k8.row.col.f32.tf32.tf32.f32 "
        "{%0,%1,%2,%3}, {%4,%5,%6,%7}, {%8,%9}, {%0,%1,%2,%3};\n"
        : "+f"(c[0]), "+f"(c[1]), "+f"(c[2]), "+f"(c[3])
        : "r"(a[0]), "r"(a[1]), "r"(a[2]), "r"(a[3]), "r"(b[0]), "r"(b[1]));
}
__device__ __forceinline__ void cp_async16(void* smem, const void* gmem) {
    uint32_t s = (uint32_t)__cvta_generic_to_shared(smem);
    asm volatile("cp.async.cg.shared.global [%0], [%1], 16;\n" :: "r"(s), "l"(gmem));
}
__device__ __forceinline__ void cp_commit() { asm volatile("cp.async.commit_group;\n"); }
__device__ __forceinline__ void cp_wait0()  { asm volatile("cp.async.wait_group 0;\n"); }

__device__ __forceinline__ void mbar_init(uint32_t a, uint32_t cnt) {
    asm volatile("mbarrier.init.shared.b64 [%0], %1;" :: "r"(a), "r"(cnt) : "memory");
}
__device__ __forceinline__ void mbar_expect_tx(uint32_t a, uint32_t tx) {
    asm volatile("mbarrier.arrive.expect_tx.shared.b64 _, [%0], %1;" :: "r"(a), "r"(tx) : "memory");
}
__device__ __forceinline__ void mbar_wait(uint32_t a, int ph) {
    asm volatile(
        "{\n\t.reg .pred P;\n\t"
        "WL_%=:\n\t"
        "mbarrier.try_wait.parity.acquire.cta.shared::cta.b64 P, [%0], %1, 0x989680;\n\t"
        "@P bra.uni WD_%=;\n\t"
        "bra.uni WL_%=;\n\t"
        "WD_%=:\n\t}" :: "r"(a), "r"(ph) : "memory");
}
__device__ __forceinline__ void tma2d(uint32_t dst, const CUtensorMap* m, int cx, int cy,
                                      uint32_t mbar) {
    asm volatile(
        "cp.async.bulk.tensor.2d.shared::cta.global.tile.mbarrier::complete_tx::bytes "
        "[%0], [%1, {%2, %3}], [%4];"
        :: "r"(dst), "l"(m), "r"(cx), "r"(cy), "r"(mbar) : "memory");
}

// ---------------- TMA GEMM body: Y = X W^T + bias -------------------------------
// 128x128 CTA tile, 128 threads (4 warps, 2x2, 64x64 warp tiles), 3-stage TMA
// pipeline with per-chunk __syncthreads (R12 best config).
// CVTA/CVTB: cvt fp32->tf32 at fragment load (A = activations, B = weights).
// cvt-at-load == pre-rounding bit-wise, so numerics are unchanged.
#define TGA(s)   (1024u + (uint32_t)(s) * 32768u)
#define TGB(s)   (TGA(s) + 16384u)
#define TGBAR(s) (64u + (uint32_t)(s) * 8u)
#define TG_SMEM_BYTES (1024 + 3 * 32768)
#define TG_NK (DD / 32)   // 32 chunks

template<bool CVTA, bool CVTB, bool RND>
__device__ __forceinline__ void gemm_body(
    const CUtensorMap* mapX, const CUtensorMap* mapW,
    const float* __restrict__ bias, float* __restrict__ Y,
    char* smem, int m0, int n0)
{
    const uint32_t sb = (uint32_t)__cvta_generic_to_shared(smem);
    const int tid = threadIdx.x;
    const int warp = tid >> 5, lane = tid & 31;
    const int g = lane >> 2, tg = lane & 3;
    const int wm = warp >> 1, wn = warp & 1;   // 2x2 warps, 64x64 tiles
    const int xg = g * 4;

    if (tid == 0) {
#pragma unroll
        for (int s = 0; s < 3; s++) mbar_init(sb + TGBAR(s), 1);
    }
    __syncthreads();

    float c[4][8][4];
#pragma unroll
    for (int i = 0; i < 4; i++)
#pragma unroll
        for (int j = 0; j < 8; j++)
#pragma unroll
            for (int t = 0; t < 4; t++) c[i][j][t] = 0.f;

    if (tid == 0) {
#pragma unroll
        for (int cch = 0; cch < 3; cch++) {
            mbar_expect_tx(sb + TGBAR(cch), 32768u);
            tma2d(sb + TGA(cch), mapX, cch * 32, m0, sb + TGBAR(cch));
            tma2d(sb + TGB(cch), mapW, cch * 32, n0, sb + TGBAR(cch));
        }
    }

    int ph[3] = {0, 0, 0};
    for (int kt = 0; kt < TG_NK; kt++) {
        const int s = (kt % 3);
        mbar_wait(sb + TGBAR(s), ph[s]); ph[s] ^= 1;

        const float* A = (const float*)(smem + TGA(s));
        const float* B = (const float*)(smem + TGB(s));
#pragma unroll
        for (int kk = 0; kk < 32; kk += 8) {
            const int c0 = (kk + tg) ^ xg;
            const int c1 = (kk + tg + 4) ^ xg;
            uint32_t a[4][4], b[8][2];
#pragma unroll
            for (int mi = 0; mi < 4; mi++) {
                const int rb = (wm * 64 + mi * 16 + g) * 32;
                if (CVTA) {
                    a[mi][0] = f2tf32(A[rb + c0]);
                    a[mi][1] = f2tf32(A[rb + 256 + c0]);
                    a[mi][2] = f2tf32(A[rb + c1]);
                    a[mi][3] = f2tf32(A[rb + 256 + c1]);
                } else {
                    a[mi][0] = __float_as_uint(A[rb + c0]);
                    a[mi][1] = __float_as_uint(A[rb + 256 + c0]);
                    a[mi][2] = __float_as_uint(A[rb + c1]);
                    a[mi][3] = __float_as_uint(A[rb + 256 + c1]);
                }
            }
#pragma unroll
            for (int nj = 0; nj < 8; nj++) {
                const int rb = (wn * 64 + nj * 8 + g) * 32;
                if (CVTB) {
                    b[nj][0] = f2tf32(B[rb + c0]);
                    b[nj][1] = f2tf32(B[rb + c1]);
                } else {
                    b[nj][0] = __float_as_uint(B[rb + c0]);
                    b[nj][1] = __float_as_uint(B[rb + c1]);
                }
            }
#pragma unroll
            for (int mi = 0; mi < 4; mi++)
#pragma unroll
                for (int nj = 0; nj < 8; nj++)
                    mma_tf32(c[mi][nj], a[mi], b[nj]);
        }
        __syncthreads();   // stage s fully consumed by all warps
        if (kt + 3 < TG_NK && tid == 0) {
            mbar_expect_tx(sb + TGBAR(s), 32768u);
            tma2d(sb + TGA(s), mapX, (kt + 3) * 32, m0, sb + TGBAR(s));
            tma2d(sb + TGB(s), mapW, (kt + 3) * 32, n0, sb + TGBAR(s));
        }
    }

    // epilogue: + bias, (RND), store
#pragma unroll
    for (int nj = 0; nj < 8; nj++) {
        const int coln = n0 + wn * 64 + nj * 8 + 2 * tg;
        const float2 bb = *(const float2*)(bias + coln);
#pragma unroll
        for (int mi = 0; mi < 4; mi++) {
            const int row = m0 + wm * 64 + mi * 16 + g;
            float y00 = c[mi][nj][0] + bb.x, y01 = c[mi][nj][1] + bb.y;
            float y10 = c[mi][nj][2] + bb.x, y11 = c[mi][nj][3] + bb.y;
            if (RND) { y00 = rndtf(y00); y01 = rndtf(y01); y10 = rndtf(y10); y11 = rndtf(y11); }
            *(float2*)(Y + (size_t)row * DD + coln)       = make_float2(y00, y01);
            *(float2*)(Y + (size_t)(row + 8) * DD + coln) = make_float2(y10, y11);
        }
    }
}

// fused Q/K/V projection GEMMs: blockIdx.z selects the problem
__global__ __launch_bounds__(128, 2) void gemm3_kernel(
    const __grid_constant__ CUtensorMap mX0, const __grid_constant__ CUtensorMap mX1,
    const __grid_constant__ CUtensorMap mX2,
    const __grid_constant__ CUtensorMap mW0, const __grid_constant__ CUtensorMap mW1,
    const __grid_constant__ CUtensorMap mW2,
    const float* __restrict__ b0, const float* __restrict__ b1, const float* __restrict__ b2,
    float* __restrict__ y0, float* __restrict__ y1, float* __restrict__ y2)
{
    extern __shared__ __align__(1024) char smem[];
    const int z = blockIdx.z;
    const CUtensorMap* mapX = (z == 0) ? &mX0 : (z == 1) ? &mX1 : &mX2;
    const CUtensorMap* mapW = (z == 0) ? &mW0 : (z == 1) ? &mW1 : &mW2;
    const float* bias       = (z == 0) ? b0 : (z == 1) ? b1 : b2;
    float* Y                = (z == 0) ? y0 : (z == 1) ? y1 : y2;
    gemm_body<true, true, true>(mapX, mapW, bias, Y, smem,
                                blockIdx.y * 128, blockIdx.x * 128);
}

// single output-projection GEMM (Ctx is tf32 bits; W needs in-loop rounding)
__global__ __launch_bounds__(128, 2) void gemm1_kernel(
    const __grid_constant__ CUtensorMap mX, const __grid_constant__ CUtensorMap mW,
    const float* __restrict__ bias, float* __restrict__ Y)
{
    extern __shared__ __align__(1024) char smem[];
    gemm_body<false, true, false>(&mX, &mW, bias, Y, smem,
                                  blockIdx.y * 128, blockIdx.x * 128);
}

// ---------------- flash attention (R5/R9 known-good, unchanged) -----------------
#define KLD 68
#define VLD 72
#define ATT_SMEM_BYTES ((2 * 64 * KLD + 2 * 64 * VLD + 128 * KLD) * 4)

__global__ __launch_bounds__(128, 2) void attn_kernel(
    const float* __restrict__ Qh, const float* __restrict__ Kh,
    const float* __restrict__ Vh, float* __restrict__ Ctx)
{
    extern __shared__ __align__(16) float sm[];
    float* Ks = sm;
    float* Vs = Ks + 2 * 64 * KLD;
    float* Ss = Vs + 2 * 64 * VLD;

    const int tid = threadIdx.x, warp = tid >> 5, lane = tid & 31;
    const int g = lane >> 2, tg = lane & 3;
    const int qt = blockIdx.x, bh = blockIdx.y;
    const int b = bh >> 4, h = bh & 15;

    const size_t rowQ0 = (size_t)(b * SS + qt * 128);
    const size_t colH  = (size_t)h * DKK;
    const float* Qg  = Qh + rowQ0 * DD + colH;
    const float* Kg0 = Kh + (size_t)(b * SS) * DD + colH;
    const float* Vg0 = Vh + (size_t)(b * SS) * DD + colH;

#define ATT_LOAD_STAGE(s, kt)                                                          \
    do {                                                                               \
        const float* Kg = Kg0 + (size_t)((kt) * 64) * DD;                              \
        const float* Vg = Vg0 + (size_t)((kt) * 64) * DD;                              \
        _Pragma("unroll")                                                              \
        for (int i = tid; i < 64 * 16; i += 128) {                                     \
            int r = i >> 4, c4 = i & 15;                                               \
            cp_async16(&Ks[(s) * 64 * KLD + r * KLD + c4 * 4],                         \
                       Kg + (size_t)r * DD + c4 * 4);                                  \
            cp_async16(&Vs[(s) * 64 * VLD + r * VLD + c4 * 4],                         \
                       Vg + (size_t)r * DD + c4 * 4);                                  \
        }                                                                              \
    } while (0)

    ATT_LOAD_STAGE(0, 0);
    cp_commit();

    float* Sw = Ss + (warp * 32) * KLD;
    {
        const float* Qw = Qg + (size_t)(warp * 32) * DD;
#pragma unroll
        for (int i = lane; i < 32 * 16; i += 32) {
            int r = i >> 4, c4 = i & 15;
            *(float4*)&Sw[r * KLD + c4 * 4] = *(const float4*)(Qw + (size_t)r * DD + c4 * 4);
        }
    }
    __syncwarp();

    uint32_t aq0[8][4], aq1[8][4];
    {
        const float scale = 0.125f;
        const int r0 = g * KLD, r1 = (g + 8) * KLD;
        const int r2 = (16 + g) * KLD, r3 = (24 + g) * KLD;
#pragma unroll
        for (int kk = 0; kk < 8; kk++) {
            aq0[kk][0] = __float_as_uint(Sw[r0 + 8 * kk + tg] * scale);
            aq0[kk][1] = __float_as_uint(Sw[r1 + 8 * kk + tg] * scale);
            aq0[kk][2] = __float_as_uint(Sw[r0 + 8 * kk + tg + 4] * scale);
            aq0[kk][3] = __float_as_uint(Sw[r1 + 8 * kk + tg + 4] * scale);
            aq1[kk][0] = __float_as_uint(Sw[r2 + 8 * kk + tg] * scale);
            aq1[kk][1] = __float_as_uint(Sw[r3 + 8 * kk + tg] * scale);
            aq1[kk][2] = __float_as_uint(Sw[r2 + 8 * kk + tg + 4] * scale);
            aq1[kk][3] = __float_as_uint(Sw[r3 + 8 * kk + tg + 4] * scale);
        }
    }
    __syncwarp();

    float o0[8][4], o1[8][4];
#pragma unroll
    for (int j = 0; j < 8; j++)
#pragma unroll
        for (int t = 0; t < 4; t++) { o0[j][t] = 0.f; o1[j][t] = 0.f; }
    float mA0 = -INFINITY, mB0 = -INFINITY, lA0 = 0.f, lB0 = 0.f;
    float mA1 = -INFINITY, mB1 = -INFINITY, lA1 = 0.f, lB1 = 0.f;

    cp_wait0();
    __syncthreads();

    for (int kt = 0; kt < SS / 64; kt++) {
        const int s = kt & 1;
        if (kt + 1 < SS / 64) { ATT_LOAD_STAGE(s ^ 1, kt + 1); cp_commit(); }

        const float* K = Ks + s * 64 * KLD;
        const float* V = Vs + s * 64 * VLD;

        float sc0[8][4], sc1[8][4];
#pragma unroll
        for (int j = 0; j < 8; j++)
#pragma unroll
            for (int t = 0; t < 4; t++) { sc0[j][t] = 0.f; sc1[j][t] = 0.f; }

#pragma unroll
        for (int kk = 0; kk < 8; kk++) {
#pragma unroll
            for (int j = 0; j < 8; j++) {
                uint32_t bfr[2];
                const int rn = (8 * j + g) * KLD + 8 * kk + tg;
                bfr[0] = __float_as_uint(K[rn]);
                bfr[1] = __float_as_uint(K[rn + 4]);
                mma_tf32(sc0[j], aq0[kk], bfr);
                mma_tf32(sc1[j], aq1[kk], bfr);
            }
        }

        float mxA0 = -INFINITY, mxB0 = -INFINITY, mxA1 = -INFINITY, mxB1 = -INFINITY;
#pragma unroll
        for (int j = 0; j < 8; j++) {
            mxA0 = fmaxf(mxA0, fmaxf(sc0[j][0], sc0[j][1]));
            mxB0 = fmaxf(mxB0, fmaxf(sc0[j][2], sc0[j][3]));
            mxA1 = fmaxf(mxA1, fmaxf(sc1[j][0], sc1[j][1]));
            mxB1 = fmaxf(mxB1, fmaxf(sc1[j][2], sc1[j][3]));
        }
#pragma unroll
        for (int off = 1; off <= 2; off <<= 1) {
            mxA0 = fmaxf(mxA0, __shfl_xor_sync(0xffffffffu, mxA0, off));
            mxB0 = fmaxf(mxB0, __shfl_xor_sync(0xffffffffu, mxB0, off));
            mxA1 = fmaxf(mxA1, __shfl_xor_sync(0xffffffffu, mxA1, off));
            mxB1 = fmaxf(mxB1, __shfl_xor_sync(0xffffffffu, mxB1, off));
        }

        const float mA0n = fmaxf(mA0, mxA0), mB0n = fmaxf(mB0, mxB0);
        const float mA1n = fmaxf(mA1, mxA1), mB1n = fmaxf(mB1, mxB1);
        const float aA0 = __expf(mA0 - mA0n), aB0 = __expf(mB0 - mB0n);
        const float aA1 = __expf(mA1 - mA1n), aB1 = __expf(mB1 - mB1n);

        float sA0 = 0.f, sB0 = 0.f, sA1 = 0.f, sB1 = 0.f;
#pragma unroll
        for (int j = 0; j < 8; j++) {
            sc0[j][0] = __expf(sc0[j][0] - mA0n);
            sc0[j][1] = __expf(sc0[j][1] - mA0n);
            sc0[j][2] = __expf(sc0[j][2] - mB0n);
            sc0[j][3] = __expf(sc0[j][3] - mB0n);
            sc1[j][0] = __expf(sc1[j][0] - mA1n);
            sc1[j][1] = __expf(sc1[j][1] - mA1n);
            sc1[j][2] = __expf(sc1[j][2] - mB1n);
            sc1[j][3] = __expf(sc1[j][3] - mB1n);
            sA0 += sc0[j][0] + sc0[j][1];
            sB0 += sc0[j][2] + sc0[j][3];
            sA1 += sc1[j][0] + sc1[j][1];
            sB1 += sc1[j][2] + sc1[j][3];
        }
#pragma unroll
        for (int off = 1; off <= 2; off <<= 1) {
            sA0 += __shfl_xor_sync(0xffffffffu, sA0, off);
            sB0 += __shfl_xor_sync(0xffffffffu, sB0, off);
            sA1 += __shfl_xor_sync(0xffffffffu, sA1, off);
            sB1 += __shfl_xor_sync(0xffffffffu, sB1, off);
        }

        lA0 = lA0 * aA0 + sA0;  mA0 = mA0n;
        lB0 = lB0 * aB0 + sB0;  mB0 = mB0n;
        lA1 = lA1 * aA1 + sA1;  mA1 = mA1n;
        lB1 = lB1 * aB1 + sB1;  mB1 = mB1n;

#pragma unroll
        for (int j = 0; j < 8; j++) {
            o0[j][0] *= aA0; o0[j][1] *= aA0; o0[j][2] *= aB0; o0[j][3] *= aB0;
            o1[j][0] *= aA1; o1[j][1] *= aA1; o1[j][2] *= aB1; o1[j][3] *= aB1;
        }

#pragma unroll
        for (int j = 0; j < 8; j++) {
            *(float2*)&Sw[g * KLD + 8 * j + 2 * tg] =
                make_float2(rndtf(sc0[j][0]), rndtf(sc0[j][1]));
            *(float2*)&Sw[(g + 8) * KLD + 8 * j + 2 * tg] =
                make_float2(rndtf(sc0[j][2]), rndtf(sc0[j][3]));
            *(float2*)&Sw[(16 + g) * KLD + 8 * j + 2 * tg] =
                make_float2(rndtf(sc1[j][0]), rndtf(sc1[j][1]));
            *(float2*)&Sw[(24 + g) * KLD + 8 * j + 2 * tg] =
                make_float2(rndtf(sc1[j][2]), rndtf(sc1[j][3]));
        }
        __syncwarp();

#pragma unroll
        for (int kk = 0; kk < 8; kk++) {
            uint32_t pa0[4], pa1[4];
            pa0[0] = __float_as_uint(Sw[g * KLD + 8 * kk + tg]);
            pa0[1] = __float_as_uint(Sw[(g + 8) * KLD + 8 * kk + tg]);
            pa0[2] = __float_as_uint(Sw[g * KLD + 8 * kk + tg + 4]);
            pa0[3] = __float_as_uint(Sw[(g + 8) * KLD + 8 * kk + tg + 4]);
            pa1[0] = __float_as_uint(Sw[(16 + g) * KLD + 8 * kk + tg]);
            pa1[1] = __float_as_uint(Sw[(24 + g) * KLD + 8 * kk + tg]);
            pa1[2] = __float_as_uint(Sw[(16 + g) * KLD + 8 * kk + tg + 4]);
            pa1[3] = __float_as_uint(Sw[(24 + g) * KLD + 8 * kk + tg + 4]);
#pragma unroll
            for (int j = 0; j < 8; j++) {
                uint32_t bfr[2];
                const int rv = (8 * kk + tg) * VLD + 8 * j + g;
                bfr[0] = __float_as_uint(V[rv]);
                bfr[1] = __float_as_uint(V[rv + 4 * VLD]);
                mma_tf32(o0[j], pa0, bfr);
                mma_tf32(o1[j], pa1, bfr);
            }
        }

        cp_wait0();
        __syncthreads();
    }

    const float iA0 = 1.f / lA0, iB0 = 1.f / lB0;
    const float iA1 = 1.f / lA1, iB1 = 1.f / lB1;
    float* Cg = Ctx + (rowQ0 + warp * 32) * DD + colH;
#pragma unroll
    for (int j = 0; j < 8; j++) {
        const int col = 8 * j + 2 * tg;
        *(float2*)(Cg + (size_t)g * DD + col) =
            make_float2(rndtf(o0[j][0] * iA0), rndtf(o0[j][1] * iA0));
        *(float2*)(Cg + (size_t)(g + 8) * DD + col) =
            make_float2(rndtf(o0[j][2] * iB0), rndtf(o0[j][3] * iB0));
        *(float2*)(Cg + (size_t)(16 + g) * DD + col) =
            make_float2(rndtf(o1[j][0] * iA1), rndtf(o1[j][1] * iA1));
        *(float2*)(Cg + (size_t)(24 + g) * DD + col) =
            make_float2(rndtf(o1[j][2] * iB1), rndtf(o1[j][3] * iB1));
    }
#undef ATT_LOAD_STAGE
}

// ---------------- host: tensor maps without -lcuda ------------------------------
typedef CUresult (*EncodeFn)(CUtensorMap*, CUtensorMapDataType, cuuint32_t, void*,
                             const cuuint64_t*, const cuuint64_t*, const cuuint32_t*,
                             const cuuint32_t*, CUtensorMapInterleave, CUtensorMapSwizzle,
                             CUtensorMapL2promotion, CUtensorMapFloatOOBfill);

static void make_map(EncodeFn enc, CUtensorMap* m, const float* ptr, uint64_t rows)
{
    cuuint64_t dims[2]    = {DD, rows};
    cuuint64_t strides[1] = {DD * sizeof(float)};
    cuuint32_t box[2]     = {32, 128};    // 32 fp32 = 128B = one SW128 row
    cuuint32_t es[2]      = {1, 1};
    enc(m, CU_TENSOR_MAP_DATA_TYPE_FLOAT32, 2, (void*)ptr, dims, strides, box, es,
        CU_TENSOR_MAP_INTERLEAVE_NONE, CU_TENSOR_MAP_SWIZZLE_128B,
        CU_TENSOR_MAP_L2_PROMOTION_L2_128B, CU_TENSOR_MAP_FLOAT_OOB_FILL_NONE);
}

extern "C" void kernel_launch(void* const* d_in, const int* /*in_sizes*/, int /*n_in*/,
                              void* d_out, int /*out_size*/)
{
    const float* q  = (const float*)d_in[0];
    const float* k  = (const float*)d_in[1];
    const float* v  = (const float*)d_in[2];
    const float* Wq = (const float*)d_in[3];
    const float* bq = (const float*)d_in[4];
    const float* Wk = (const float*)d_in[5];
    const float* bk = (const float*)d_in[6];
    const float* Wv = (const float*)d_in[7];
    const float* bv = (const float*)d_in[8];
    const float* Wo = (const float*)d_in[9];
    const float* bo = (const float*)d_in[10];
    float* out = (float*)d_out;

    float *Qh, *Kh, *Vh, *Ctx;
    cudaGetSymbolAddress((void**)&Qh,  g_Qh);
    cudaGetSymbolAddress((void**)&Kh,  g_Kh);
    cudaGetSymbolAddress((void**)&Vh,  g_Vh);
    cudaGetSymbolAddress((void**)&Ctx, g_Ctx);

    static EncodeFn enc = nullptr;
    if (!enc) {
        void* p = nullptr;
        cudaDriverEntryPointQueryResult st;
        cudaGetDriverEntryPointByVersion("cuTensorMapEncodeTiled", &p, 12000,
                                         cudaEnableDefault, &st);
        enc = (EncodeFn)p;
    }
    CUtensorMap mXq, mXk, mXv, mWq, mWk, mWv, mWo, mCtx;
    make_map(enc, &mXq, q, MM);  make_map(enc, &mXk, k, MM);
    make_map(enc, &mXv, v, MM);  make_map(enc, &mCtx, Ctx, MM);
    make_map(enc, &mWq, Wq, DD); make_map(enc, &mWk, Wk, DD);
    make_map(enc, &mWv, Wv, DD); make_map(enc, &mWo, Wo, DD);

    cudaFuncSetAttribute(gemm3_kernel,
                         cudaFuncAttributeMaxDynamicSharedMemorySize, TG_SMEM_BYTES);
    cudaFuncSetAttribute(gemm1_kernel,
                         cudaFuncAttributeMaxDynamicSharedMemorySize, TG_SMEM_BYTES);
    cudaFuncSetAttribute(attn_kernel,
                         cudaFuncAttributeMaxDynamicSharedMemorySize, ATT_SMEM_BYTES);

    // fused Q/K/V projections: one launch, 768 blocks of 128 threads.
    // Weight tf32 rounding is fused into the B-fragment loads (CVTB).
    gemm3_kernel<<<dim3(DD / 128, MM / 128, 3), 128, TG_SMEM_BYTES>>>(
        mXq, mXk, mXv, mWq, mWk, mWv, bq, bk, bv, Qh, Kh, Vh);

    attn_kernel<<<dim3(SS / 128, BB * HH), 128, ATT_SMEM_BYTES>>>(Qh, Kh, Vh, Ctx);

    gemm1_kernel<<<dim3(DD / 128, MM / 128), 128, TG_SMEM_BYTES>>>(mCtx, mWo, bo, out);
}

// round 16
// speedup vs baseline: 1.0214x; 1.0214x over previous
#include <cuda_runtime.h>
#include <cuda.h>
#include <math.h>
#include <stdint.h>

#define BB   2
#define SS   2048
#define DD   1024
#define HH   16
#define DKK  64
#define MM   (BB * SS)

__device__ float g_Qh[MM * DD];
__device__ float g_Kh[MM * DD];
__device__ float g_Vh[MM * DD];
__device__ float g_Ctx[MM * DD];
__device__ float g_Wqr[DD * DD];
__device__ float g_Wkr[DD * DD];
__device__ float g_Wvr[DD * DD];
__device__ float g_Wor[DD * DD];

// ---------------- PTX helpers --------------------------------------------------
__device__ __forceinline__ uint32_t f2tf32(float x) {
    uint32_t r; asm("cvt.rna.tf32.f32 %0, %1;\n" : "=r"(r) : "f"(x)); return r;
}
__device__ __forceinline__ float rndtf(float x) { return __uint_as_float(f2tf32(x)); }

__device__ __forceinline__ void mma_tf32(float c[4], const uint32_t a[4], const uint32_t b[2]) {
    asm volatile(
        "mma.sync.aligned.m16n8k8.row.col.f32.tf32.tf32.f32 "
        "{%0,%1,%2,%3}, {%4,%5,%6,%7}, {%8,%9}, {%0,%1,%2,%3};\n"
        : "+f"(c[0]), "+f"(c[1]), "+f"(c[2]), "+f"(c[3])
        : "r"(a[0]), "r"(a[1]), "r"(a[2]), "r"(a[3]), "r"(b[0]), "r"(b[1]));
}
__device__ __forceinline__ void cp_async16(void* smem, const void* gmem) {
    uint32_t s = (uint32_t)__cvta_generic_to_shared(smem);
    asm volatile("cp.async.cg.shared.global [%0], [%1], 16;\n" :: "r"(s), "l"(gmem));
}
__device__ __forceinline__ void cp_commit() { asm volatile("cp.async.commit_group;\n"); }
__device__ __forceinline__ void cp_wait0()  { asm volatile("cp.async.wait_group 0;\n"); }

__device__ __forceinline__ void mbar_init(uint32_t a, uint32_t cnt) {
    asm volatile("mbarrier.init.shared.b64 [%0], %1;" :: "r"(a), "r"(cnt) : "memory");
}
__device__ __forceinline__ void mbar_expect_tx(uint32_t a, uint32_t tx) {
    asm volatile("mbarrier.arrive.expect_tx.shared.b64 _, [%0], %1;" :: "r"(a), "r"(tx) : "memory");
}
__device__ __forceinline__ void mbar_wait(uint32_t a, int ph) {
    asm volatile(
        "{\n\t.reg .pred P;\n\t"
        "WL_%=:\n\t"
        "mbarrier.try_wait.parity.acquire.cta.shared::cta.b64 P, [%0], %1, 0x989680;\n\t"
        "@P bra.uni WD_%=;\n\t"
        "bra.uni WL_%=;\n\t"
        "WD_%=:\n\t}" :: "r"(a), "r"(ph) : "memory");
}
__device__ __forceinline__ void tma2d(uint32_t dst, const CUtensorMap* m, int cx, int cy,
                                      uint32_t mbar) {
    asm volatile(
        "cp.async.bulk.tensor.2d.shared::cta.global.tile.mbarrier::complete_tx::bytes "
        "[%0], [%1, {%2, %3}], [%4];"
        :: "r"(dst), "l"(m), "r"(cx), "r"(cy), "r"(mbar) : "memory");
}

// ---------------- batched tf32 pre-round of the 4 weight matrices ---------------
__global__ void round4_kernel(const float* __restrict__ a, const float* __restrict__ b,
                              const float* __restrict__ c, const float* __restrict__ d,
                              float* __restrict__ oa, float* __restrict__ ob,
                              float* __restrict__ oc, float* __restrict__ od)
{
    const float* s = (blockIdx.y == 0) ? a : (blockIdx.y == 1) ? b : (blockIdx.y == 2) ? c : d;
    float* o       = (blockIdx.y == 0) ? oa : (blockIdx.y == 1) ? ob : (blockIdx.y == 2) ? oc : od;
    const int i = blockIdx.x * blockDim.x + threadIdx.x;
    float4 v = ((const float4*)s)[i];
    v.x = rndtf(v.x); v.y = rndtf(v.y); v.z = rndtf(v.z); v.w = rndtf(v.w);
    ((float4*)o)[i] = v;
}

// ---------------- TMA GEMM body: Y = X W^T + bias -------------------------------
// 128x128 CTA tile, 128 threads (4 warps, 2x2, 64x64 warp tiles), 3-stage TMA
// pipeline, TWO chunks consumed per __syncthreads (16 syncs instead of 32).
// Chunk c lives in stage c%3; after sync, the producer refills the two consumed
// stages with chunks c+3, c+4 (same stage arithmetic). Chunk order unchanged.
// CVTA: cvt A fp32->tf32 at fragment load (X raw). Weights are pre-rounded.
#define TGA(s)   (1024u + (uint32_t)(s) * 32768u)
#define TGB(s)   (TGA(s) + 16384u)
#define TGBAR(s) (64u + (uint32_t)(s) * 8u)
#define TG_SMEM_BYTES (1024 + 3 * 32768)
#define TG_NK (DD / 32)   // 32 chunks (even)

template<bool CVTA, bool RND>
__device__ __forceinline__ void gemm_body(
    const CUtensorMap* mapX, const CUtensorMap* mapW,
    const float* __restrict__ bias, float* __restrict__ Y,
    char* smem, int m0, int n0)
{
    const uint32_t sb = (uint32_t)__cvta_generic_to_shared(smem);
    const int tid = threadIdx.x;
    const int warp = tid >> 5, lane = tid & 31;
    const int g = lane >> 2, tg = lane & 3;
    const int wm = warp >> 1, wn = warp & 1;   // 2x2 warps, 64x64 tiles
    const int xg = g * 4;

    if (tid == 0) {
#pragma unroll
        for (int s = 0; s < 3; s++) mbar_init(sb + TGBAR(s), 1);
    }
    __syncthreads();

    float c[4][8][4];
#pragma unroll
    for (int i = 0; i < 4; i++)
#pragma unroll
        for (int j = 0; j < 8; j++)
#pragma unroll
            for (int t = 0; t < 4; t++) c[i][j][t] = 0.f;

    if (tid == 0) {
#pragma unroll
        for (int cch = 0; cch < 3; cch++) {
            mbar_expect_tx(sb + TGBAR(cch), 32768u);
            tma2d(sb + TGA(cch), mapX, cch * 32, m0, sb + TGBAR(cch));
            tma2d(sb + TGB(cch), mapW, cch * 32, n0, sb + TGBAR(cch));
        }
    }

    int ph[3] = {0, 0, 0};

#define GEMM_CONSUME(sidx)                                                             \
    do {                                                                               \
        mbar_wait(sb + TGBAR(sidx), ph[sidx]); ph[sidx] ^= 1;                          \
        const float* A = (const float*)(smem + TGA(sidx));                             \
        const float* B = (const float*)(smem + TGB(sidx));                             \
        _Pragma("unroll")                                                              \
        for (int kk = 0; kk < 32; kk += 8) {                                           \
            const int c0 = (kk + tg) ^ xg;                                             \
            const int c1 = (kk + tg + 4) ^ xg;                                         \
            uint32_t a[4][4], b[8][2];                                                 \
            _Pragma("unroll")                                                          \
            for (int mi = 0; mi < 4; mi++) {                                           \
                const int rb = (wm * 64 + mi * 16 + g) * 32;                           \
                if (CVTA) {                                                            \
                    a[mi][0] = f2tf32(A[rb + c0]);                                     \
                    a[mi][1] = f2tf32(A[rb + 256 + c0]);                               \
                    a[mi][2] = f2tf32(A[rb + c1]);                                     \
                    a[mi][3] = f2tf32(A[rb + 256 + c1]);                               \
                } else {                                                               \
                    a[mi][0] = __float_as_uint(A[rb + c0]);                            \
                    a[mi][1] = __float_as_uint(A[rb + 256 + c0]);                      \
                    a[mi][2] = __float_as_uint(A[rb + c1]);                            \
                    a[mi][3] = __float_as_uint(A[rb + 256 + c1]);                      \
                }                                                                      \
            }                                                                          \
            _Pragma("unroll")                                                          \
            for (int nj = 0; nj < 8; nj++) {                                           \
                const int rb = (wn * 64 + nj * 8 + g) * 32;                            \
                b[nj][0] = __float_as_uint(B[rb + c0]);                                \
                b[nj][1] = __float_as_uint(B[rb + c1]);                                \
            }                                                                          \
            _Pragma("unroll")                                                          \
            for (int mi = 0; mi < 4; mi++)                                             \
                _Pragma("unroll")                                                      \
                for (int nj = 0; nj < 8; nj++)                                         \
                    mma_tf32(c[mi][nj], a[mi], b[nj]);                                 \
        }                                                                              \
    } while (0)

    for (int kt = 0; kt < TG_NK; kt += 2) {
        const int s0 = kt % 3, s1 = (kt + 1) % 3;
        GEMM_CONSUME(s0);
        GEMM_CONSUME(s1);
        __syncthreads();   // both stages fully consumed by all warps
        if (tid == 0) {
            if (kt + 3 < TG_NK) {
                mbar_expect_tx(sb + TGBAR(s0), 32768u);
                tma2d(sb + TGA(s0), mapX, (kt + 3) * 32, m0, sb + TGBAR(s0));
                tma2d(sb + TGB(s0), mapW, (kt + 3) * 32, n0, sb + TGBAR(s0));
            }
            if (kt + 4 < TG_NK) {
                mbar_expect_tx(sb + TGBAR(s1), 32768u);
                tma2d(sb + TGA(s1), mapX, (kt + 4) * 32, m0, sb + TGBAR(s1));
                tma2d(sb + TGB(s1), mapW, (kt + 4) * 32, n0, sb + TGBAR(s1));
            }
        }
    }
#undef GEMM_CONSUME

    // epilogue: + bias, (RND), store
#pragma unroll
    for (int nj = 0; nj < 8; nj++) {
        const int coln = n0 + wn * 64 + nj * 8 + 2 * tg;
        const float2 bb = *(const float2*)(bias + coln);
#pragma unroll
        for (int mi = 0; mi < 4; mi++) {
            const int row = m0 + wm * 64 + mi * 16 + g;
            float y00 = c[mi][nj][0] + bb.x, y01 = c[mi][nj][1] + bb.y;
            float y10 = c[mi][nj][2] + bb.x, y11 = c[mi][nj][3] + bb.y;
            if (RND) { y00 = rndtf(y00); y01 = rndtf(y01); y10 = rndtf(y10); y11 = rndtf(y11); }
            *(float2*)(Y + (size_t)row * DD + coln)       = make_float2(y00, y01);
            *(float2*)(Y + (size_t)(row + 8) * DD + coln) = make_float2(y10, y11);
        }
    }
}

// fused Q/K/V projection GEMMs: blockIdx.z selects the problem
__global__ __launch_bounds__(128, 2) void gemm3_kernel(
    const __grid_constant__ CUtensorMap mX0, const __grid_constant__ CUtensorMap mX1,
    const __grid_constant__ CUtensorMap mX2,
    const __grid_constant__ CUtensorMap mW0, const __grid_constant__ CUtensorMap mW1,
    const __grid_constant__ CUtensorMap mW2,
    const float* __restrict__ b0, const float* __restrict__ b1, const float* __restrict__ b2,
    float* __restrict__ y0, float* __restrict__ y1, float* __restrict__ y2)
{
    extern __shared__ __align__(1024) char smem[];
    const int z = blockIdx.z;
    const CUtensorMap* mapX = (z == 0) ? &mX0 : (z == 1) ? &mX1 : &mX2;
    const CUtensorMap* mapW = (z == 0) ? &mW0 : (z == 1) ? &mW1 : &mW2;
    const float* bias       = (z == 0) ? b0 : (z == 1) ? b1 : b2;
    float* Y                = (z == 0) ? y0 : (z == 1) ? y1 : y2;
    gemm_body<true, true>(mapX, mapW, bias, Y, smem,
                          blockIdx.y * 128, blockIdx.x * 128);
}

// single output-projection GEMM (Ctx and Wor are already tf32 bits)
__global__ __launch_bounds__(128, 2) void gemm1_kernel(
    const __grid_constant__ CUtensorMap mX, const __grid_constant__ CUtensorMap mW,
    const float* __restrict__ bias, float* __restrict__ Y)
{
    extern __shared__ __align__(1024) char smem[];
    gemm_body<false, false>(&mX, &mW, bias, Y, smem,
                            blockIdx.y * 128, blockIdx.x * 128);
}

// ---------------- flash attention (R5/R9 known-good, unchanged) -----------------
#define KLD 68
#define VLD 72
#define ATT_SMEM_BYTES ((2 * 64 * KLD + 2 * 64 * VLD + 128 * KLD) * 4)

__global__ __launch_bounds__(128, 2) void attn_kernel(
    const float* __restrict__ Qh, const float* __restrict__ Kh,
    const float* __restrict__ Vh, float* __restrict__ Ctx)
{
    extern __shared__ __align__(16) float sm[];
    float* Ks = sm;
    float* Vs = Ks + 2 * 64 * KLD;
    float* Ss = Vs + 2 * 64 * VLD;

    const int tid = threadIdx.x, warp = tid >> 5, lane = tid & 31;
    const int g = lane >> 2, tg = lane & 3;
    const int qt = blockIdx.x, bh = blockIdx.y;
    const int b = bh >> 4, h = bh & 15;

    const size_t rowQ0 = (size_t)(b * SS + qt * 128);
    const size_t colH  = (size_t)h * DKK;
    const float* Qg  = Qh + rowQ0 * DD + colH;
    const float* Kg0 = Kh + (size_t)(b * SS) * DD + colH;
    const float* Vg0 = Vh + (size_t)(b * SS) * DD + colH;

#define ATT_LOAD_STAGE(s, kt)                                                          \
    do {                                                                               \
        const float* Kg = Kg0 + (size_t)((kt) * 64) * DD;                              \
        const float* Vg = Vg0 + (size_t)((kt) * 64) * DD;                              \
        _Pragma("unroll")                                                              \
        for (int i = tid; i < 64 * 16; i += 128) {                                     \
            int r = i >> 4, c4 = i & 15;                                               \
            cp_async16(&Ks[(s) * 64 * KLD + r * KLD + c4 * 4],                         \
                       Kg + (size_t)r * DD + c4 * 4);                                  \
            cp_async16(&Vs[(s) * 64 * VLD + r * VLD + c4 * 4],                         \
                       Vg + (size_t)r * DD + c4 * 4);                                  \
        }                                                                              \
    } while (0)

    ATT_LOAD_STAGE(0, 0);
    cp_commit();

    float* Sw = Ss + (warp * 32) * KLD;
    {
        const float* Qw = Qg + (size_t)(warp * 32) * DD;
#pragma unroll
        for (int i = lane; i < 32 * 16; i += 32) {
            int r = i >> 4, c4 = i & 15;
            *(float4*)&Sw[r * KLD + c4 * 4] = *(const float4*)(Qw + (size_t)r * DD + c4 * 4);
        }
    }
    __syncwarp();

    uint32_t aq0[8][4], aq1[8][4];
    {
        const float scale = 0.125f;
        const int r0 = g * KLD, r1 = (g + 8) * KLD;
        const int r2 = (16 + g) * KLD, r3 = (24 + g) * KLD;
#pragma unroll
        for (int kk = 0; kk < 8; kk++) {
            aq0[kk][0] = __float_as_uint(Sw[r0 + 8 * kk + tg] * scale);
            aq0[kk][1] = __float_as_uint(Sw[r1 + 8 * kk + tg] * scale);
            aq0[kk][2] = __float_as_uint(Sw[r0 + 8 * kk + tg + 4] * scale);
            aq0[kk][3] = __float_as_uint(Sw[r1 + 8 * kk + tg + 4] * scale);
            aq1[kk][0] = __float_as_uint(Sw[r2 + 8 * kk + tg] * scale);
            aq1[kk][1] = __float_as_uint(Sw[r3 + 8 * kk + tg] * scale);
            aq1[kk][2] = __float_as_uint(Sw[r2 + 8 * kk + tg + 4] * scale);
            aq1[kk][3] = __float_as_uint(Sw[r3 + 8 * kk + tg + 4] * scale);
        }
    }
    __syncwarp();

    float o0[8][4], o1[8][4];
#pragma unroll
    for (int j = 0; j < 8; j++)
#pragma unroll
        for (int t = 0; t < 4; t++) { o0[j][t] = 0.f; o1[j][t] = 0.f; }
    float mA0 = -INFINITY, mB0 = -INFINITY, lA0 = 0.f, lB0 = 0.f;
    float mA1 = -INFINITY, mB1 = -INFINITY, lA1 = 0.f, lB1 = 0.f;

    cp_wait0();
    __syncthreads();

    for (int kt = 0; kt < SS / 64; kt++) {
        const int s = kt & 1;
        if (kt + 1 < SS / 64) { ATT_LOAD_STAGE(s ^ 1, kt + 1); cp_commit(); }

        const float* K = Ks + s * 64 * KLD;
        const float* V = Vs + s * 64 * VLD;

        float sc0[8][4], sc1[8][4];
#pragma unroll
        for (int j = 0; j < 8; j++)
#pragma unroll
            for (int t = 0; t < 4; t++) { sc0[j][t] = 0.f; sc1[j][t] = 0.f; }

#pragma unroll
        for (int kk = 0; kk < 8; kk++) {
#pragma unroll
            for (int j = 0; j < 8; j++) {
                uint32_t bfr[2];
                const int rn = (8 * j + g) * KLD + 8 * kk + tg;
                bfr[0] = __float_as_uint(K[rn]);
                bfr[1] = __float_as_uint(K[rn + 4]);
                mma_tf32(sc0[j], aq0[kk], bfr);
                mma_tf32(sc1[j], aq1[kk], bfr);
            }
        }

        float mxA0 = -INFINITY, mxB0 = -INFINITY, mxA1 = -INFINITY, mxB1 = -INFINITY;
#pragma unroll
        for (int j = 0; j < 8; j++) {
            mxA0 = fmaxf(mxA0, fmaxf(sc0[j][0], sc0[j][1]));
            mxB0 = fmaxf(mxB0, fmaxf(sc0[j][2], sc0[j][3]));
            mxA1 = fmaxf(mxA1, fmaxf(sc1[j][0], sc1[j][1]));
            mxB1 = fmaxf(mxB1, fmaxf(sc1[j][2], sc1[j][3]));
        }
#pragma unroll
        for (int off = 1; off <= 2; off <<= 1) {
            mxA0 = fmaxf(mxA0, __shfl_xor_sync(0xffffffffu, mxA0, off));
            mxB0 = fmaxf(mxB0, __shfl_xor_sync(0xffffffffu, mxB0, off));
            mxA1 = fmaxf(mxA1, __shfl_xor_sync(0xffffffffu, mxA1, off));
            mxB1 = fmaxf(mxB1, __shfl_xor_sync(0xffffffffu, mxB1, off));
        }

        const float mA0n = fmaxf(mA0, mxA0), mB0n = fmaxf(mB0, mxB0);
        const float mA1n = fmaxf(mA1, mxA1), mB1n = fmaxf(mB1, mxB1);
        const float aA0 = __expf(mA0 - mA0n), aB0 = __expf(mB0 - mB0n);
        const float aA1 = __expf(mA1 - mA1n), aB1 = __expf(mB1 - mB1n);

        float sA0 = 0.f, sB0 = 0.f, sA1 = 0.f, sB1 = 0.f;
#pragma unroll
        for (int j = 0; j < 8; j++) {
            sc0[j][0] = __expf(sc0[j][0] - mA0n);
            sc0[j][1] = __expf(sc0[j][1] - mA0n);
            sc0[j][2] = __expf(sc0[j][2] - mB0n);
            sc0[j][3] = __expf(sc0[j][3] - mB0n);
            sc1[j][0] = __expf(sc1[j][0] - mA1n);
            sc1[j][1] = __expf(sc1[j][1] - mA1n);
            sc1[j][2] = __expf(sc1[j][2] - mB1n);
            sc1[j][3] = __expf(sc1[j][3] - mB1n);
            sA0 += sc0[j][0] + sc0[j][1];
            sB0 += sc0[j][2] + sc0[j][3];
            sA1 += sc1[j][0] + sc1[j][1];
            sB1 += sc1[j][2] + sc1[j][3];
        }
#pragma unroll
        for (int off = 1; off <= 2; off <<= 1) {
            sA0 += __shfl_xor_sync(0xffffffffu, sA0, off);
            sB0 += __shfl_xor_sync(0xffffffffu, sB0, off);
            sA1 += __shfl_xor_sync(0xffffffffu, sA1, off);
            sB1 += __shfl_xor_sync(0xffffffffu, sB1, off);
        }

        lA0 = lA0 * aA0 + sA0;  mA0 = mA0n;
        lB0 = lB0 * aB0 + sB0;  mB0 = mB0n;
        lA1 = lA1 * aA1 + sA1;  mA1 = mA1n;
        lB1 = lB1 * aB1 + sB1;  mB1 = mB1n;

#pragma unroll
        for (int j = 0; j < 8; j++) {
            o0[j][0] *= aA0; o0[j][1] *= aA0; o0[j][2] *= aB0; o0[j][3] *= aB0;
            o1[j][0] *= aA1; o1[j][1] *= aA1; o1[j][2] *= aB1; o1[j][3] *= aB1;
        }

#pragma unroll
        for (int j = 0; j < 8; j++) {
            *(float2*)&Sw[g * KLD + 8 * j + 2 * tg] =
                make_float2(rndtf(sc0[j][0]), rndtf(sc0[j][1]));
            *(float2*)&Sw[(g + 8) * KLD + 8 * j + 2 * tg] =
                make_float2(rndtf(sc0[j][2]), rndtf(sc0[j][3]));
            *(float2*)&Sw[(16 + g) * KLD + 8 * j + 2 * tg] =
                make_float2(rndtf(sc1[j][0]), rndtf(sc1[j][1]));
            *(float2*)&Sw[(24 + g) * KLD + 8 * j + 2 * tg] =
                make_float2(rndtf(sc1[j][2]), rndtf(sc1[j][3]));
        }
        __syncwarp();

#pragma unroll
        for (int kk = 0; kk < 8; kk++) {
            uint32_t pa0[4], pa1[4];
            pa0[0] = __float_as_uint(Sw[g * KLD + 8 * kk + tg]);
            pa0[1] = __float_as_uint(Sw[(g + 8) * KLD + 8 * kk + tg]);
            pa0[2] = __float_as_uint(Sw[g * KLD + 8 * kk + tg + 4]);
            pa0[3] = __float_as_uint(Sw[(g + 8) * KLD + 8 * kk + tg + 4]);
            pa1[0] = __float_as_uint(Sw[(16 + g) * KLD + 8 * kk + tg]);
            pa1[1] = __float_as_uint(Sw[(24 + g) * KLD + 8 * kk + tg]);
            pa1[2] = __float_as_uint(Sw[(16 + g) * KLD + 8 * kk + tg + 4]);
            pa1[3] = __float_as_uint(Sw[(24 + g) * KLD + 8 * kk + tg + 4]);
#pragma unroll
            for (int j = 0; j < 8; j++) {
                uint32_t bfr[2];
                const int rv = (8 * kk + tg) * VLD + 8 * j + g;
                bfr[0] = __float_as_uint(V[rv]);
                bfr[1] = __float_as_uint(V[rv + 4 * VLD]);
                mma_tf32(o0[j], pa0, bfr);
                mma_tf32(o1[j], pa1, bfr);
            }
        }

        cp_wait0();
        __syncthreads();
    }

    const float iA0 = 1.f / lA0, iB0 = 1.f / lB0;
    const float iA1 = 1.f / lA1, iB1 = 1.f / lB1;
    float* Cg = Ctx + (rowQ0 + warp * 32) * DD + colH;
#pragma unroll
    for (int j = 0; j < 8; j++) {
        const int col = 8 * j + 2 * tg;
        *(float2*)(Cg + (size_t)g * DD + col) =
            make_float2(rndtf(o0[j][0] * iA0), rndtf(o0[j][1] * iA0));
        *(float2*)(Cg + (size_t)(g + 8) * DD + col) =
            make_float2(rndtf(o0[j][2] * iB0), rndtf(o0[j][3] * iB0));
        *(float2*)(Cg + (size_t)(16 + g) * DD + col) =
            make_float2(rndtf(o1[j][0] * iA1), rndtf(o1[j][1] * iA1));
        *(float2*)(Cg + (size_t)(24 + g) * DD + col) =
            make_float2(rndtf(o1[j][2] * iB1), rndtf(o1[j][3] * iB1));
    }
#undef ATT_LOAD_STAGE
}

// ---------------- host: tensor maps without -lcuda ------------------------------
typedef CUresult (*EncodeFn)(CUtensorMap*, CUtensorMapDataType, cuuint32_t, void*,
                             const cuuint64_t*, const cuuint64_t*, const cuuint32_t*,
                             const cuuint32_t*, CUtensorMapInterleave, CUtensorMapSwizzle,
                             CUtensorMapL2promotion, CUtensorMapFloatOOBfill);

static void make_map(EncodeFn enc, CUtensorMap* m, const float* ptr, uint64_t rows)
{
    cuuint64_t dims[2]    = {DD, rows};
    cuuint64_t strides[1] = {DD * sizeof(float)};
    cuuint32_t box[2]     = {32, 128};    // 32 fp32 = 128B = one SW128 row
    cuuint32_t es[2]      = {1, 1};
    enc(m, CU_TENSOR_MAP_DATA_TYPE_FLOAT32, 2, (void*)ptr, dims, strides, box, es,
        CU_TENSOR_MAP_INTERLEAVE_NONE, CU_TENSOR_MAP_SWIZZLE_128B,
        CU_TENSOR_MAP_L2_PROMOTION_L2_128B, CU_TENSOR_MAP_FLOAT_OOB_FILL_NONE);
}

extern "C" void kernel_launch(void* const* d_in, const int* /*in_sizes*/, int /*n_in*/,
                              void* d_out, int /*out_size*/)
{
    const float* q  = (const float*)d_in[0];
    const float* k  = (const float*)d_in[1];
    const float* v  = (const float*)d_in[2];
    const float* Wq = (const float*)d_in[3];
    const float* bq = (const float*)d_in[4];
    const float* Wk = (const float*)d_in[5];
    const float* bk = (const float*)d_in[6];
    const float* Wv = (const float*)d_in[7];
    const float* bv = (const float*)d_in[8];
    const float* Wo = (const float*)d_in[9];
    const float* bo = (const float*)d_in[10];
    float* out = (float*)d_out;

    float *Qh, *Kh, *Vh, *Ctx, *Wqr, *Wkr, *Wvr, *Wor;
    cudaGetSymbolAddress((void**)&Qh,  g_Qh);
    cudaGetSymbolAddress((void**)&Kh,  g_Kh);
    cudaGetSymbolAddress((void**)&Vh,  g_Vh);
    cudaGetSymbolAddress((void**)&Ctx, g_Ctx);
    cudaGetSymbolAddress((void**)&Wqr, g_Wqr);
    cudaGetSymbolAddress((void**)&Wkr, g_Wkr);
    cudaGetSymbolAddress((void**)&Wvr, g_Wvr);
    cudaGetSymbolAddress((void**)&Wor, g_Wor);

    static EncodeFn enc = nullptr;
    if (!enc) {
        void* p = nullptr;
        cudaDriverEntryPointQueryResult st;
        cudaGetDriverEntryPointByVersion("cuTensorMapEncodeTiled", &p, 12000,
                                         cudaEnableDefault, &st);
        enc = (EncodeFn)p;
    }
    CUtensorMap mXq, mXk, mXv, mWq, mWk, mWv, mWo, mCtx;
    make_map(enc, &mXq, q, MM);   make_map(enc, &mXk, k, MM);
    make_map(enc, &mXv, v, MM);   make_map(enc, &mCtx, Ctx, MM);
    make_map(enc, &mWq, Wqr, DD); make_map(enc, &mWk, Wkr, DD);
    make_map(enc, &mWv, Wvr, DD); make_map(enc, &mWo, Wor, DD);

    cudaFuncSetAttribute(gemm3_kernel,
                         cudaFuncAttributeMaxDynamicSharedMemorySize, TG_SMEM_BYTES);
    cudaFuncSetAttribute(gemm1_kernel,
                         cudaFuncAttributeMaxDynamicSharedMemorySize, TG_SMEM_BYTES);
    cudaFuncSetAttribute(attn_kernel,
                         cudaFuncAttributeMaxDynamicSharedMemorySize, ATT_SMEM_BYTES);

    // pre-round the weights to tf32 bits (R12 scheme: keeps GEMM loops cvt-light)
    round4_kernel<<<dim3((DD * DD / 4) / 256, 4), 256>>>(Wq, Wk, Wv, Wo, Wqr, Wkr, Wvr, Wor);

    // fused Q/K/V projections: one launch, 768 blocks of 128 threads
    gemm3_kernel<<<dim3(DD / 128, MM / 128, 3), 128, TG_SMEM_BYTES>>>(
        mXq, mXk, mXv, mWq, mWk, mWv, bq, bk, bv, Qh, Kh, Vh);

    attn_kernel<<<dim3(SS / 128, BB * HH), 128, ATT_SMEM_BYTES>>>(Qh, Kh, Vh, Ctx);

    gemm1_kernel<<<dim3(DD / 128, MM / 128), 128, TG_SMEM_BYTES>>>(mCtx, mWo, bo, out);
}